// round 14
// baseline (speedup 1.0000x reference)
#include <cuda_runtime.h>
#include <cuda_fp16.h>
#include <cstdint>

#define N_NODES   100000
#define N_EDGES   1600000
#define EDGE_FEAT 16
#define EDGE_HID  32
#define NODE_FEAT 128
#define K_STR     168     // smem K stride (elem): 84 words/row, conflict-free ldmatrix
#define NUM_TILES 782     // ceil(100000/128)

// Scratch (allocation-free rule: __device__ globals)
__device__ float g_wsum[N_NODES * EDGE_FEAT];
__device__ float g_ssum[N_NODES];
__device__ unsigned g_tile;                    // work-stealing counter
// fp16 weights, [n][k] (transposed), zero-padded to K_STR
__device__ __half g_W1f[128 * K_STR];
__device__ __half g_W2f[128 * K_STR];

__device__ __forceinline__ uint32_t sm32(const void* p) {
    return (uint32_t)__cvta_generic_to_shared(p);
}
__device__ __forceinline__ uint32_t h2bits(float a, float b) {
    __half2 h = __floats2half2_rn(a, b);
    return *reinterpret_cast<uint32_t*>(&h);
}
__device__ __forceinline__ void mma16816(float* d, const uint32_t* a,
                                         uint32_t b0, uint32_t b1) {
    asm volatile(
        "mma.sync.aligned.m16n8k16.row.col.f32.f16.f16.f32 "
        "{%0,%1,%2,%3}, {%4,%5,%6,%7}, {%8,%9}, {%0,%1,%2,%3};"
        : "+f"(d[0]), "+f"(d[1]), "+f"(d[2]), "+f"(d[3])
        : "r"(a[0]), "r"(a[1]), "r"(a[2]), "r"(a[3]), "r"(b0), "r"(b1));
}
__device__ __forceinline__ void ldm4(uint32_t* r, uint32_t addr) {
    asm volatile("ldmatrix.sync.aligned.m8n8.x4.shared.b16 {%0,%1,%2,%3}, [%4];"
                 : "=r"(r[0]), "=r"(r[1]), "=r"(r[2]), "=r"(r[3]) : "r"(addr));
}
__device__ __forceinline__ void cp16(uint32_t dst, const void* src) {
    asm volatile("cp.async.cg.shared.global [%0], [%1], 16;"
                 :: "r"(dst), "l"(src));
}
#define CP_COMMIT() asm volatile("cp.async.commit_group;" ::: "memory")
#define CP_WAIT0()  asm volatile("cp.async.wait_group 0;" ::: "memory")

// ------------------------------------------- prep: zero scratch + fp16 weights
__global__ void prep_kernel(const float* __restrict__ W1,
                            const float* __restrict__ W2) {
    int i = blockIdx.x * blockDim.x + threadIdx.x;
    if (i == 0) g_tile = 0;                    // reset work counter each launch
    int stride = gridDim.x * blockDim.x;
    float4 z = make_float4(0.f, 0.f, 0.f, 0.f);
    float4* a = reinterpret_cast<float4*>(g_wsum);
    for (int idx = i; idx < N_NODES * EDGE_FEAT / 4; idx += stride) a[idx] = z;
    float4* b = reinterpret_cast<float4*>(g_ssum);
    for (int idx = i; idx < N_NODES / 4; idx += stride) b[idx] = z;
    if (i < 128 * K_STR) {
        int n = i / K_STR, k = i % K_STR;
        g_W1f[i] = __float2half_rn((k < 160) ? W1[k * 128 + n] : 0.f);
        g_W2f[i] = __float2half_rn((k < 128) ? W2[k * 128 + n] : 0.f);
    }
}

// ------------------------------------------------- edge pass: scatter ex, ex*f
__global__ void edge_kernel(const float* __restrict__ logits,
                            const float4* __restrict__ feats4,
                            const int* __restrict__ dst) {
    int t = blockIdx.x * blockDim.x + threadIdx.x;
    int e = t >> 2;
    int q = t & 3;
    if (e >= N_EDGES) return;
    int d = dst[e];
    float ex = __expf(logits[e]);
    float4 f = feats4[e * 4 + q];
    f.x *= ex; f.y *= ex; f.z *= ex; f.w *= ex;
    float* p = g_wsum + d * EDGE_FEAT + q * 4;
    asm volatile("red.global.add.v4.f32 [%0], {%1,%2,%3,%4};"
                 :: "l"(p), "f"(f.x), "f"(f.y), "f"(f.z), "f"(f.w) : "memory");
    if (q == 0)
        asm volatile("red.global.add.f32 [%0], %1;"
                     :: "l"(g_ssum + d), "f"(ex) : "memory");
}

// ---------------------------------------------------------------- fused MLP
// Persistent work-stealing blocks, single-pass fp16 HMMA, cp.async prefetch of
// next tile's raw inputs (nf/wsum/ssum) overlapped with the current tile's GEMMs.
// W1+W2 smem-resident for the whole kernel. 512 threads, 4x4 warp grid.
template<int KSTEPS>
__device__ __forceinline__ void gemm1p(uint32_t aA, uint32_t bA,
                                       int lid, int wm, int wn,
                                       float acc[2][4][4]) {
    const uint32_t aOff = ((wm * 32 + (lid & 15)) * K_STR + 8 * (lid >> 4)) * 2;
    const uint32_t bOff = ((wn * 32 + ((lid >> 4) << 3) + (lid & 7)) * K_STR
                           + 8 * ((lid >> 3) & 1)) * 2;
#pragma unroll 2
    for (int ks = 0; ks < KSTEPS; ks++) {
        uint32_t a[2][4], b[2][4];
#pragma unroll
        for (int mf = 0; mf < 2; mf++)
            ldm4(a[mf], aA + aOff + mf * 16 * K_STR * 2 + ks * 32);
#pragma unroll
        for (int pb = 0; pb < 2; pb++)
            ldm4(b[pb], bA + bOff + pb * 16 * K_STR * 2 + ks * 32);
#pragma unroll
        for (int pb = 0; pb < 2; pb++)
#pragma unroll
            for (int h = 0; h < 2; h++)
#pragma unroll
                for (int mf = 0; mf < 2; mf++)
                    mma16816(acc[mf][pb * 2 + h], a[mf], b[pb][2 * h], b[pb][2 * h + 1]);
    }
}

__device__ __forceinline__ void prefetch_tile(int tile, uint32_t nfA, uint32_t wsA,
                                              uint32_t ssA, const float* nf, int tid) {
    long node0 = (long)tile * 128;
#pragma unroll
    for (int i = tid; i < 4096; i += 512) {        // nf: 64KB
        long src = node0 * 128 + (long)i * 4;
        if (src > (long)N_NODES * 128 - 4) src = (long)N_NODES * 128 - 4;
        cp16(nfA + i * 16, nf + src);
    }
    {                                              // wsum: 8KB
        int i = tid & 511;
        if (i < 512) {
            long src = node0 * 16 + (long)i * 4;
            if (src > (long)N_NODES * 16 - 4) src = (long)N_NODES * 16 - 4;
            cp16(wsA + i * 16, g_wsum + src);
        }
    }
    if (tid < 32) {                                // ssum: 512B
        long src = node0 + (long)tid * 4;
        if (src > (long)N_NODES - 4) src = (long)N_NODES - 4;
        cp16(ssA + tid * 16, g_ssum + src);
    }
}

// smem: 3*128*168*2 (B1,B2,A) + (16384+2048+128+128+128+512+32)*4 = 206464
#define SMEM_BYTES 206464

__global__ __launch_bounds__(512, 1)
void mlp_kernel(const float* __restrict__ nf,
                const float* __restrict__ W_et, const float* __restrict__ b_et,
                const float* __restrict__ b1, const float* __restrict__ b2,
                float* __restrict__ out) {
    extern __shared__ char smem[];
    __half* B1f = reinterpret_cast<__half*>(smem);
    __half* B2f = B1f + 128 * K_STR;
    __half* Af  = B2f + 128 * K_STR;
    float* nfbuf = reinterpret_cast<float*>(Af + 128 * K_STR);   // [128][128]
    float* wsbuf = nfbuf + 16384;                                // [128][16]
    float* ssbuf = wsbuf + 2048;                                 // [128]
    float* b1s   = ssbuf + 128;
    float* b2s   = b1s + 128;
    float* Wets  = b2s + 128;          // [16][32]
    float* bets  = Wets + 512;         // [32]
    __shared__ int s_tile;

    const int tid = threadIdx.x;
    const int wid = tid >> 5, lid = tid & 31;
    const int wm = wid >> 2, wn = wid & 3;   // 4x4 warp grid, 32x32 tiles
    const int g = lid >> 2, tg = lid & 3;
    const uint32_t afA = sm32(Af), b1A = sm32(B1f), b2A = sm32(B2f);
    const uint32_t nfA = sm32(nfbuf), wsA = sm32(wsbuf), ssA = sm32(ssbuf);

    if (tid == 0) s_tile = (int)atomicAdd(&g_tile, 1u);
    {   // both weight matrices via cp.async, ONCE
        const char* s1 = reinterpret_cast<const char*>(g_W1f);
        const char* s2 = reinterpret_cast<const char*>(g_W2f);
#pragma unroll
        for (int i = tid; i < 2688; i += 512) {
            cp16(b1A + i * 16, s1 + i * 16);
            cp16(b2A + i * 16, s2 + i * 16);
        }
    }
    if (tid < 128) { b1s[tid] = b1[tid]; b2s[tid] = b2[tid]; }
    if (tid < 512) Wets[tid] = W_et[tid];
    if (tid < 32) bets[tid] = b_et[tid];
    __syncthreads();                           // s_tile visible
    int tile = s_tile;
    if (tile < NUM_TILES) prefetch_tile(tile, nfA, wsA, ssA, nf, tid);
    CP_COMMIT();

    const float4* nb4 = reinterpret_cast<const float4*>(nfbuf);
    const float4* wb4 = reinterpret_cast<const float4*>(wsbuf);

    for (;;) {
        if (tile >= NUM_TILES) break;
        CP_WAIT0();
        __syncthreads();                       // prefetched data ready; prev GEMM2 done
        const int node0 = tile * 128;

        {   // A staging from smem buffers: ctx inline (8 cols) + nf (32 cols), fp16
            int row = tid >> 2, q = tid & 3;
            float s = ssbuf[row];
            float inv = (s > 0.f) ? (1.f / s) : 0.f;
            float ind = (s > 0.f) ? 1.f : 0.f;
            float gv[16];
#pragma unroll
            for (int k4 = 0; k4 < 4; k4++) {
                float4 v = wb4[row * 4 + k4];
                gv[k4 * 4 + 0] = v.x * inv; gv[k4 * 4 + 1] = v.y * inv;
                gv[k4 * 4 + 2] = v.z * inv; gv[k4 * 4 + 3] = v.w * inv;
            }
            float c[8];
            const int j0 = 8 * q;
#pragma unroll
            for (int j = 0; j < 8; j++) c[j] = ind * bets[j0 + j];
#pragma unroll
            for (int k = 0; k < 16; k++) {
                float a = gv[k];
#pragma unroll
                for (int j = 0; j < 8; j++) c[j] = fmaf(a, Wets[k * 32 + j0 + j], c[j]);
            }
#pragma unroll
            for (int j = 0; j < 8; j++) c[j] = (c[j] > 0.f) ? c[j] : (__expf(c[j]) - 1.0f);
            uint4 u;
            u.x = h2bits(c[0], c[1]); u.y = h2bits(c[2], c[3]);
            u.z = h2bits(c[4], c[5]); u.w = h2bits(c[6], c[7]);
            *reinterpret_cast<uint4*>(&Af[row * K_STR + j0]) = u;
            int kb = 32 + 32 * q;
#pragma unroll
            for (int j = 0; j < 8; j++) {
                float4 v = nb4[row * 32 + 8 * q + j];
                uint2 w;
                w.x = h2bits(v.x, v.y); w.y = h2bits(v.z, v.w);
                *reinterpret_cast<uint2*>(&Af[row * K_STR + kb + 4 * j]) = w;
            }
        }
        if (tid == 0) s_tile = (int)atomicAdd(&g_tile, 1u);
        __syncthreads();                       // Af ready; s_tile visible; buffers free
        const int next = s_tile;
        if (next < NUM_TILES) prefetch_tile(next, nfA, wsA, ssA, nf, tid);
        CP_COMMIT();                           // lands during GEMMs below

        float acc[2][4][4];
#pragma unroll
        for (int a = 0; a < 2; a++)
#pragma unroll
            for (int b = 0; b < 4; b++)
#pragma unroll
                for (int c = 0; c < 4; c++) acc[a][b][c] = 0.f;

        // GEMM1: K=160 (10 k-steps), single-pass fp16
        gemm1p<10>(afA, b1A, lid, wm, wn, acc);
        __syncthreads();                       // all GEMM1 reads of Af done

        // epilogue 1: bias+relu -> H (fp16) into Af ([m][n] as new [m][k])
#pragma unroll
        for (int mf = 0; mf < 2; mf++) {
#pragma unroll
            for (int nfi = 0; nfi < 4; nfi++) {
                int n = wn * 32 + nfi * 8 + 2 * tg;
                int m = wm * 32 + mf * 16 + g;
                float x0 = fmaxf(acc[mf][nfi][0] + b1s[n],     0.f);
                float x1 = fmaxf(acc[mf][nfi][1] + b1s[n + 1], 0.f);
                *reinterpret_cast<uint32_t*>(&Af[m * K_STR + n]) = h2bits(x0, x1);
                float x2 = fmaxf(acc[mf][nfi][2] + b1s[n],     0.f);
                float x3 = fmaxf(acc[mf][nfi][3] + b1s[n + 1], 0.f);
                *reinterpret_cast<uint32_t*>(&Af[(m + 8) * K_STR + n]) = h2bits(x2, x3);
            }
        }
        __syncthreads();

#pragma unroll
        for (int a = 0; a < 2; a++)
#pragma unroll
            for (int b = 0; b < 4; b++)
#pragma unroll
                for (int c = 0; c < 4; c++) acc[a][b][c] = 0.f;

        // GEMM2: K=128 (8 k-steps), single-pass fp16
        gemm1p<8>(afA, b2A, lid, wm, wn, acc);

        // epilogue 2: bias+relu -> out
#pragma unroll
        for (int mf = 0; mf < 2; mf++) {
#pragma unroll
            for (int nfi = 0; nfi < 4; nfi++) {
                int n = wn * 32 + nfi * 8 + 2 * tg;
                int m = node0 + wm * 32 + mf * 16 + g;
                if (m < N_NODES) {
                    float2 v;
                    v.x = fmaxf(acc[mf][nfi][0] + b2s[n],     0.f);
                    v.y = fmaxf(acc[mf][nfi][1] + b2s[n + 1], 0.f);
                    *reinterpret_cast<float2*>(&out[m * 128 + n]) = v;
                }
                if (m + 8 < N_NODES) {
                    float2 v;
                    v.x = fmaxf(acc[mf][nfi][2] + b2s[n],     0.f);
                    v.y = fmaxf(acc[mf][nfi][3] + b2s[n + 1], 0.f);
                    *reinterpret_cast<float2*>(&out[(m + 8) * 128 + n]) = v;
                }
            }
        }
        tile = next;
    }
}

extern "C" void kernel_launch(void* const* d_in, const int* in_sizes, int n_in,
                              void* d_out, int out_size) {
    const float* edge_logits = (const float*)d_in[0];
    const float* edge_feats  = (const float*)d_in[1];
    const float* node_feats  = (const float*)d_in[2];
    const int*   dst         = (const int*)d_in[3];
    const float* W_et        = (const float*)d_in[4];
    const float* b_et        = (const float*)d_in[5];
    const float* W1          = (const float*)d_in[6];
    const float* b1          = (const float*)d_in[7];
    const float* W2          = (const float*)d_in[8];
    const float* b2          = (const float*)d_in[9];
    float* out = (float*)d_out;

    cudaFuncSetAttribute(mlp_kernel, cudaFuncAttributeMaxDynamicSharedMemorySize,
                         SMEM_BYTES);

    prep_kernel<<<1024, 256>>>(W1, W2);
    edge_kernel<<<(N_EDGES * 4) / 256, 256>>>(edge_logits,
                                              (const float4*)edge_feats, dst);
    mlp_kernel<<<152, 512, SMEM_BYTES>>>(node_feats, W_et, b_et, b1, b2, out);
    (void)in_sizes; (void)n_in; (void)out_size;
}

// round 15
// speedup vs baseline: 1.5714x; 1.5714x over previous
#include <cuda_runtime.h>
#include <cuda_fp16.h>
#include <cstdint>

#define N_NODES   100000
#define N_EDGES   1600000
#define EDGE_FEAT 16
#define EDGE_HID  32
#define NODE_FEAT 128
#define K_STR     168     // smem K stride (elem): 84 words/row, conflict-free ldmatrix
#define NUM_TILES 782     // ceil(100000/128)

// Scratch (allocation-free rule: __device__ globals)
__device__ float g_wsum[N_NODES * EDGE_FEAT];
__device__ float g_ssum[N_NODES];
__device__ unsigned g_tile;                    // work-stealing counter
// fp16 weights, [n][k] (transposed), zero-padded to K_STR
__device__ __half g_W1f[128 * K_STR];
__device__ __half g_W2f[128 * K_STR];

__device__ __forceinline__ uint32_t sm32(const void* p) {
    return (uint32_t)__cvta_generic_to_shared(p);
}
__device__ __forceinline__ uint32_t h2bits(float a, float b) {
    __half2 h = __floats2half2_rn(a, b);
    return *reinterpret_cast<uint32_t*>(&h);
}
__device__ __forceinline__ void mma16816(float* d, const uint32_t* a,
                                         uint32_t b0, uint32_t b1) {
    asm volatile(
        "mma.sync.aligned.m16n8k16.row.col.f32.f16.f16.f32 "
        "{%0,%1,%2,%3}, {%4,%5,%6,%7}, {%8,%9}, {%0,%1,%2,%3};"
        : "+f"(d[0]), "+f"(d[1]), "+f"(d[2]), "+f"(d[3])
        : "r"(a[0]), "r"(a[1]), "r"(a[2]), "r"(a[3]), "r"(b0), "r"(b1));
}
__device__ __forceinline__ void ldm4(uint32_t* r, uint32_t addr) {
    asm volatile("ldmatrix.sync.aligned.m8n8.x4.shared.b16 {%0,%1,%2,%3}, [%4];"
                 : "=r"(r[0]), "=r"(r[1]), "=r"(r[2]), "=r"(r[3]) : "r"(addr));
}
__device__ __forceinline__ void cp16(uint32_t dst, const void* src) {
    asm volatile("cp.async.cg.shared.global [%0], [%1], 16;"
                 :: "r"(dst), "l"(src));
}
#define CP_COMMIT() asm volatile("cp.async.commit_group;" ::: "memory")
#define CP_WAIT0()  asm volatile("cp.async.wait_group 0;" ::: "memory")

// ------------------------------------------- prep: zero scratch + fp16 weights
__global__ void prep_kernel(const float* __restrict__ W1,
                            const float* __restrict__ W2) {
    int i = blockIdx.x * blockDim.x + threadIdx.x;
    if (i == 0) g_tile = 0;                    // reset work counter each launch
    int stride = gridDim.x * blockDim.x;
    float4 z = make_float4(0.f, 0.f, 0.f, 0.f);
    float4* a = reinterpret_cast<float4*>(g_wsum);
    for (int idx = i; idx < N_NODES * EDGE_FEAT / 4; idx += stride) a[idx] = z;
    float4* b = reinterpret_cast<float4*>(g_ssum);
    for (int idx = i; idx < N_NODES / 4; idx += stride) b[idx] = z;
    if (i < 128 * K_STR) {
        int n = i / K_STR, k = i % K_STR;
        g_W1f[i] = __float2half_rn((k < 160) ? W1[k * 128 + n] : 0.f);
        g_W2f[i] = __float2half_rn((k < 128) ? W2[k * 128 + n] : 0.f);
    }
}

// ------------------------------------------------- edge pass: scatter ex, ex*f
__global__ void edge_kernel(const float* __restrict__ logits,
                            const float4* __restrict__ feats4,
                            const int* __restrict__ dst) {
    int t = blockIdx.x * blockDim.x + threadIdx.x;
    int e = t >> 2;
    int q = t & 3;
    if (e >= N_EDGES) return;
    int d = dst[e];
    float ex = __expf(logits[e]);
    float4 f = feats4[e * 4 + q];
    f.x *= ex; f.y *= ex; f.z *= ex; f.w *= ex;
    float* p = g_wsum + d * EDGE_FEAT + q * 4;
    asm volatile("red.global.add.v4.f32 [%0], {%1,%2,%3,%4};"
                 :: "l"(p), "f"(f.x), "f"(f.y), "f"(f.z), "f"(f.w) : "memory");
    if (q == 0)
        asm volatile("red.global.add.f32 [%0], %1;"
                     :: "l"(g_ssum + d), "f"(ex) : "memory");
}

// ---------------------------------------------------------------- fused MLP
// Persistent work-stealing blocks, single-pass fp16 HMMA (C = Af16 @ Bf16),
// direct-LDG staging (R13 structure), W1+W2 smem-resident for the whole kernel.
// 512 threads, 4x4 warp grid, 32x32 warp tiles per 128x128 node tile.
template<int KSTEPS>
__device__ __forceinline__ void gemm1p(uint32_t aA, uint32_t bA,
                                       int lid, int wm, int wn,
                                       float acc[2][4][4]) {
    const uint32_t aOff = ((wm * 32 + (lid & 15)) * K_STR + 8 * (lid >> 4)) * 2;
    const uint32_t bOff = ((wn * 32 + ((lid >> 4) << 3) + (lid & 7)) * K_STR
                           + 8 * ((lid >> 3) & 1)) * 2;
#pragma unroll 2
    for (int ks = 0; ks < KSTEPS; ks++) {
        uint32_t a[2][4], b[2][4];
#pragma unroll
        for (int mf = 0; mf < 2; mf++)
            ldm4(a[mf], aA + aOff + mf * 16 * K_STR * 2 + ks * 32);
#pragma unroll
        for (int pb = 0; pb < 2; pb++)
            ldm4(b[pb], bA + bOff + pb * 16 * K_STR * 2 + ks * 32);
#pragma unroll
        for (int pb = 0; pb < 2; pb++)
#pragma unroll
            for (int h = 0; h < 2; h++)
#pragma unroll
                for (int mf = 0; mf < 2; mf++)
                    mma16816(acc[mf][pb * 2 + h], a[mf], b[pb][2 * h], b[pb][2 * h + 1]);
    }
}

// smem: 3*128*168*2 (B1,B2,Af) + (128+128+512+32)*4 = 132224
#define SMEM_BYTES 132224

__global__ __launch_bounds__(512, 1)
void mlp_kernel(const float* __restrict__ nf,
                const float* __restrict__ W_et, const float* __restrict__ b_et,
                const float* __restrict__ b1, const float* __restrict__ b2,
                float* __restrict__ out) {
    extern __shared__ char smem[];
    __half* B1f = reinterpret_cast<__half*>(smem);
    __half* B2f = B1f + 128 * K_STR;
    __half* Af  = B2f + 128 * K_STR;
    float* b1s  = reinterpret_cast<float*>(Af + 128 * K_STR);
    float* b2s  = b1s + 128;
    float* Wets = b2s + 128;          // [16][32]
    float* bets = Wets + 512;         // [32]
    __shared__ int s_tile;

    const int tid = threadIdx.x;
    const int wid = tid >> 5, lid = tid & 31;
    const int wm = wid >> 2, wn = wid & 3;   // 4x4 warp grid, 32x32 tiles
    const int g = lid >> 2, tg = lid & 3;
    const uint32_t afA = sm32(Af), b1A = sm32(B1f), b2A = sm32(B2f);

    {   // both weight matrices via cp.async, ONCE for the whole kernel
        const char* s1 = reinterpret_cast<const char*>(g_W1f);
        const char* s2 = reinterpret_cast<const char*>(g_W2f);
#pragma unroll
        for (int i = tid; i < 2688; i += 512) {
            cp16(b1A + i * 16, s1 + i * 16);
            cp16(b2A + i * 16, s2 + i * 16);
        }
        CP_COMMIT();
    }
    if (tid < 128) { b1s[tid] = b1[tid]; b2s[tid] = b2[tid]; }
    if (tid < 512) Wets[tid] = W_et[tid];
    if (tid < 32) bets[tid] = b_et[tid];

    const float4* nf4 = reinterpret_cast<const float4*>(nf);

    for (;;) {
        if (tid == 0) s_tile = (int)atomicAdd(&g_tile, 1u);
        __syncthreads();                      // counter visible; prev GEMM2 reads done
        const int tile = s_tile;
        if (tile >= NUM_TILES) break;
        const int node0 = tile * 128;

        {   // A staging: 4 threads/row; ctx inline (8 cols) + nf (32 cols), fp16
            int row = tid >> 2, q = tid & 3;
            int node = node0 + row;
            if (node >= N_NODES) node = N_NODES - 1;   // clamp; out stores guarded
            float s = g_ssum[node];
            float inv = (s > 0.f) ? (1.f / s) : 0.f;
            float ind = (s > 0.f) ? 1.f : 0.f;
            float gv[16];
            const float4* gp = reinterpret_cast<const float4*>(g_wsum + node * 16);
#pragma unroll
            for (int k4 = 0; k4 < 4; k4++) {
                float4 v = gp[k4];
                gv[k4 * 4 + 0] = v.x * inv; gv[k4 * 4 + 1] = v.y * inv;
                gv[k4 * 4 + 2] = v.z * inv; gv[k4 * 4 + 3] = v.w * inv;
            }
            float c[8];
            const int j0 = 8 * q;
#pragma unroll
            for (int j = 0; j < 8; j++) c[j] = ind * bets[j0 + j];
#pragma unroll
            for (int k = 0; k < 16; k++) {
                float a = gv[k];
#pragma unroll
                for (int j = 0; j < 8; j++) c[j] = fmaf(a, Wets[k * 32 + j0 + j], c[j]);
            }
#pragma unroll
            for (int j = 0; j < 8; j++) c[j] = (c[j] > 0.f) ? c[j] : (__expf(c[j]) - 1.0f);
            uint4 u;
            u.x = h2bits(c[0], c[1]); u.y = h2bits(c[2], c[3]);
            u.z = h2bits(c[4], c[5]); u.w = h2bits(c[6], c[7]);
            *reinterpret_cast<uint4*>(&Af[row * K_STR + j0]) = u;
            int kb = 32 + 32 * q;
#pragma unroll
            for (int j = 0; j < 8; j++) {
                int k = kb + 4 * j;
                float4 v = nf4[node * 32 + ((k - 32) >> 2)];
                uint2 w;
                w.x = h2bits(v.x, v.y); w.y = h2bits(v.z, v.w);
                *reinterpret_cast<uint2*>(&Af[row * K_STR + k]) = w;
            }
        }
        CP_WAIT0();                           // weights ready (no-op after tile 1)
        __syncthreads();

        float acc[2][4][4];
#pragma unroll
        for (int a = 0; a < 2; a++)
#pragma unroll
            for (int b = 0; b < 4; b++)
#pragma unroll
                for (int c = 0; c < 4; c++) acc[a][b][c] = 0.f;

        // GEMM1: K=160 (10 k-steps), single-pass fp16
        gemm1p<10>(afA, b1A, lid, wm, wn, acc);
        __syncthreads();                      // all GEMM1 reads of Af done

        // epilogue 1: bias+relu -> H (fp16) into Af ([m][n] as new [m][k])
#pragma unroll
        for (int mf = 0; mf < 2; mf++) {
#pragma unroll
            for (int nfi = 0; nfi < 4; nfi++) {
                int n = wn * 32 + nfi * 8 + 2 * tg;
                int m = wm * 32 + mf * 16 + g;
                float x0 = fmaxf(acc[mf][nfi][0] + b1s[n],     0.f);
                float x1 = fmaxf(acc[mf][nfi][1] + b1s[n + 1], 0.f);
                *reinterpret_cast<uint32_t*>(&Af[m * K_STR + n]) = h2bits(x0, x1);
                float x2 = fmaxf(acc[mf][nfi][2] + b1s[n],     0.f);
                float x3 = fmaxf(acc[mf][nfi][3] + b1s[n + 1], 0.f);
                *reinterpret_cast<uint32_t*>(&Af[(m + 8) * K_STR + n]) = h2bits(x2, x3);
            }
        }
        __syncthreads();

#pragma unroll
        for (int a = 0; a < 2; a++)
#pragma unroll
            for (int b = 0; b < 4; b++)
#pragma unroll
                for (int c = 0; c < 4; c++) acc[a][b][c] = 0.f;

        // GEMM2: K=128 (8 k-steps), single-pass fp16
        gemm1p<8>(afA, b2A, lid, wm, wn, acc);

        // epilogue 2: bias+relu -> out
#pragma unroll
        for (int mf = 0; mf < 2; mf++) {
#pragma unroll
            for (int nfi = 0; nfi < 4; nfi++) {
                int n = wn * 32 + nfi * 8 + 2 * tg;
                int m = node0 + wm * 32 + mf * 16 + g;
                if (m < N_NODES) {
                    float2 v;
                    v.x = fmaxf(acc[mf][nfi][0] + b2s[n],     0.f);
                    v.y = fmaxf(acc[mf][nfi][1] + b2s[n + 1], 0.f);
                    *reinterpret_cast<float2*>(&out[m * 128 + n]) = v;
                }
                if (m + 8 < N_NODES) {
                    float2 v;
                    v.x = fmaxf(acc[mf][nfi][2] + b2s[n],     0.f);
                    v.y = fmaxf(acc[mf][nfi][3] + b2s[n + 1], 0.f);
                    *reinterpret_cast<float2*>(&out[(m + 8) * 128 + n]) = v;
                }
            }
        }
    }
}

extern "C" void kernel_launch(void* const* d_in, const int* in_sizes, int n_in,
                              void* d_out, int out_size) {
    const float* edge_logits = (const float*)d_in[0];
    const float* edge_feats  = (const float*)d_in[1];
    const float* node_feats  = (const float*)d_in[2];
    const int*   dst         = (const int*)d_in[3];
    const float* W_et        = (const float*)d_in[4];
    const float* b_et        = (const float*)d_in[5];
    const float* W1          = (const float*)d_in[6];
    const float* b1          = (const float*)d_in[7];
    const float* W2          = (const float*)d_in[8];
    const float* b2          = (const float*)d_in[9];
    float* out = (float*)d_out;

    cudaFuncSetAttribute(mlp_kernel, cudaFuncAttributeMaxDynamicSharedMemorySize,
                         SMEM_BYTES);

    prep_kernel<<<1024, 256>>>(W1, W2);
    edge_kernel<<<(N_EDGES * 4) / 256, 256>>>(edge_logits,
                                              (const float4*)edge_feats, dst);
    mlp_kernel<<<160, 512, SMEM_BYTES>>>(node_feats, W_et, b_et, b1, b2, out);
    (void)in_sizes; (void)n_in; (void)out_size;
}